// round 5
// baseline (speedup 1.0000x reference)
#include <cuda_runtime.h>
#include <cstdint>

#define NB   8
#define CCH  256      // channels
#define SP   4096     // spatial positions per batch (16^3)
#define NROW 32768    // NB*SP
#define KCB  1024     // codebook size

#define ZQ_SIZE   8388608
#define LOSS_OFF  8388608
#define PERP_OFF  8388609
#define IDX_OFF   8388610
#define FULL_OUT  8421378

__device__ float  g_S[NROW];       // |z_n|^2 (fp32)
__device__ float  g_esq[KCB];      // |e_k|^2 (fp32)
__device__ int    g_idx[NROW];
__device__ int    g_counts[KCB];
__device__ double g_losspart[1024];

// ---------------------------------------------------------------------------
// Kernel A: per-row |z|^2, per-code |e|^2, zero counts
// ---------------------------------------------------------------------------
__global__ void prep_kernel(const float* __restrict__ z,
                            const float* __restrict__ emb) {
    int bi  = blockIdx.x;
    int tid = threadIdx.x;
    if (bi < 128) {
        int n0 = bi * 256;
        int b  = n0 >> 12;
        int s  = (n0 & 4095) + tid;
        const float* zb = z + (size_t)b * CCH * SP + s;
        float acc = 0.f;
        #pragma unroll 8
        for (int c = 0; c < CCH; c++) {
            float v = zb[(size_t)c * SP];
            acc = __fmaf_rn(v, v, acc);
        }
        g_S[n0 + tid] = acc;
    } else if (bi < 132) {
        int k = (bi - 128) * 256 + tid;
        const float* er = emb + (size_t)k * CCH;
        float acc = 0.f;
        #pragma unroll 8
        for (int c = 0; c < CCH; c++) {
            float v = er[c];
            acc = __fmaf_rn(v, v, acc);
        }
        g_esq[k] = acc;
    } else {
        for (int k = tid; k < KCB; k += 256) g_counts[k] = 0;
    }
}

// ---------------------------------------------------------------------------
// Kernel B: distance GEMM + argmin, packed fp32x2 FMA (fma.rn.f32x2)
//   block: 256 threads = 16 (k-dir) x 16 (s-dir), thread tile 8s x 8k
//   s-dim paired into f32x2 lanes: 4 accumulator pairs x 8 k
//   e-tile stored pre-duplicated (e,e) in smem -> b-operand is direct LDS
// ---------------------------------------------------------------------------
#define BS 128
#define BK 128
#define TC 16

__device__ __forceinline__ unsigned int float_key(float f) {
    unsigned int u = __float_as_uint(f);
    return (u & 0x80000000u) ? ~u : (u | 0x80000000u);
}

__global__ __launch_bounds__(256, 2)
void argmin_kernel(const float* __restrict__ z,
                   const float* __restrict__ emb) {
    __shared__ __align__(16) float  zs[TC][BS];          // 8 KB
    __shared__ __align__(16) float2 es2[TC][BK];         // 16 KB, (e,e) duplicated
    __shared__ unsigned long long best[BS];              // 1 KB

    int tid = threadIdx.x;
    int n0  = blockIdx.x * BS;
    int b   = n0 >> 12;
    int s0  = n0 & 4095;
    int kt  = tid & 15;        // k-group (8 codes)
    int st  = tid >> 4;        // s-group (8 rows = 4 f32x2 pairs)

    if (tid < BS) best[tid] = 0xFFFFFFFFFFFFFFFFULL;

    float Ss[8];
    #pragma unroll
    for (int i = 0; i < 8; i++) Ss[i] = g_S[n0 + st * 8 + i];

    const float* zb = z + (size_t)b * CCH * SP + s0;

    for (int kc = 0; kc < KCB / BK; kc++) {
        int k0 = kc * BK;
        // accp[ip][j]: lanes = rows (st*8+2ip, st*8+2ip+1), code k0+kt*8+j
        unsigned long long accp[4][8];
        #pragma unroll
        for (int ip = 0; ip < 4; ip++)
            #pragma unroll
            for (int j = 0; j < 8; j++) accp[ip][j] = 0ULL;

        #pragma unroll 1
        for (int cc = 0; cc < CCH / TC; cc++) {
            int c0 = cc * TC;
            __syncthreads();
            // load z chunk [TC x BS], coalesced float4 over s
            #pragma unroll
            for (int i = tid; i < (TC * BS) / 4; i += 256) {
                int c  = i >> 5;
                int sq = i & 31;
                float4 v = *(const float4*)(zb + (size_t)(c0 + c) * SP + sq * 4);
                *(float4*)&zs[c][sq * 4] = v;
            }
            // load e chunk [BK x TC], store transposed AND duplicated: es2[c][k]=(e,e)
            #pragma unroll
            for (int i = tid; i < (BK * TC) / 4; i += 256) {
                int kk = i & 127;
                int cq = i >> 7;          // 0..1 per pass, covers c-groups of 4
                float4 v = *(const float4*)(emb + (size_t)(k0 + kk) * CCH + c0 + cq * 4);
                es2[cq * 4 + 0][kk] = make_float2(v.x, v.x);
                es2[cq * 4 + 1][kk] = make_float2(v.y, v.y);
                es2[cq * 4 + 2][kk] = make_float2(v.z, v.z);
                es2[cq * 4 + 3][kk] = make_float2(v.w, v.w);
            }
            __syncthreads();

            #pragma unroll
            for (int c = 0; c < TC; c++) {
                // a-operands: 4 s-row pairs, direct 64-bit LDS (broadcast across kt)
                unsigned long long za[4];
                #pragma unroll
                for (int ip = 0; ip < 4; ip++)
                    za[ip] = *(const unsigned long long*)&zs[c][st * 8 + 2 * ip];
                // b-operands: 8 duplicated codes, 2 per LDS.128
                unsigned long long erd[8];
                #pragma unroll
                for (int jj = 0; jj < 4; jj++) {
                    ulonglong2 t = *(const ulonglong2*)&es2[c][kt * 8 + 2 * jj];
                    erd[2 * jj]     = t.x;
                    erd[2 * jj + 1] = t.y;
                }
                #pragma unroll
                for (int ip = 0; ip < 4; ip++)
                    #pragma unroll
                    for (int j = 0; j < 8; j++)
                        asm volatile("fma.rn.f32x2 %0, %1, %2, %0;"
                                     : "+l"(accp[ip][j])
                                     : "l"(za[ip]), "l"(erd[j]));
            }
        }

        // epilogue for this k-chunk: d = fl(fl(S+esq) - 2m), exact eager rounding
        float eq[8];
        #pragma unroll
        for (int j = 0; j < 8; j++) eq[j] = g_esq[k0 + kt * 8 + j];

        #pragma unroll
        for (int ip = 0; ip < 4; ip++) {
            #pragma unroll
            for (int l = 0; l < 2; l++) {
                int i = ip * 2 + l;
                float bv = __int_as_float(0x7f800000); // +inf
                int   bk = 0;
                #pragma unroll
                for (int j = 0; j < 8; j++) {
                    float2 m2 = *(float2*)&accp[ip][j];
                    float  m  = l ? m2.y : m2.x;
                    float  t  = __fadd_rn(Ss[i], eq[j]);        // fl(S + esq)
                    float  v  = __fmaf_rn(-2.0f, m, t);         // fl(t - 2m)
                    if (v < bv) { bv = v; bk = k0 + kt * 8 + j; }
                }
                unsigned long long key =
                    ((unsigned long long)float_key(bv) << 32) | (unsigned int)bk;
                atomicMin(&best[st * 8 + i], key);
            }
        }
    }

    __syncthreads();
    if (tid < BS) {
        g_idx[n0 + tid] = (int)(best[tid] & 0xFFFFFFFFu);
    }
}

// ---------------------------------------------------------------------------
// Kernel C: STE output, counts, loss partial sums (deterministic per-block slot)
// ---------------------------------------------------------------------------
__global__ __launch_bounds__(256)
void epilogue_kernel(const float* __restrict__ z,
                     const float* __restrict__ emb,
                     float* __restrict__ out,
                     int has_extras) {
    __shared__ float  es[32][257];
    __shared__ int    sidx[32];
    __shared__ double red[256];

    int tid = threadIdx.x;
    int n0  = blockIdx.x * 32;
    int b   = n0 >> 12;
    int s0  = n0 & 4095;

    if (tid < 32) sidx[tid] = g_idx[n0 + tid];
    __syncthreads();

    for (int i = tid; i < 32 * 64; i += 256) {
        int r = i >> 6;
        int q = i & 63;
        float4 v = *(const float4*)(emb + (size_t)sidx[r] * CCH + q * 4);
        es[r][q * 4 + 0] = v.x;
        es[r][q * 4 + 1] = v.y;
        es[r][q * 4 + 2] = v.z;
        es[r][q * 4 + 3] = v.w;
    }
    if (tid < 32) atomicAdd(&g_counts[sidx[tid]], 1);
    __syncthreads();

    int s  = tid & 31;
    int cb = tid >> 5;
    const float* zb = z   + (size_t)b * CCH * SP + s0;
    float*       ob = out + (size_t)b * CCH * SP + s0;

    float lacc = 0.f;
    #pragma unroll 4
    for (int c0 = 0; c0 < CCH; c0 += 8) {
        int c = c0 + cb;
        float zv = zb[(size_t)c * SP + s];
        float ev = es[s][c];
        float d  = __fadd_rn(ev, -zv);               // fl(z_q - z)
        lacc = __fmaf_rn(d, d, lacc);
        ob[(size_t)c * SP + s] = __fadd_rn(zv, d);   // STE: fl(z + fl(z_q - z))
    }

    if (has_extras && tid < 32) {
        out[IDX_OFF + n0 + tid] = (float)sidx[tid];
    }

    red[tid] = (double)lacc;
    __syncthreads();
    for (int off = 128; off > 0; off >>= 1) {
        if (tid < off) red[tid] += red[tid + off];
        __syncthreads();
    }
    if (tid == 0) g_losspart[blockIdx.x] = red[0];
}

// ---------------------------------------------------------------------------
// Kernel D: final loss + perplexity (deterministic tree reductions)
// ---------------------------------------------------------------------------
__global__ __launch_bounds__(1024)
void finalize_kernel(float* __restrict__ out, int has_extras) {
    __shared__ double sd[1024];
    int tid = threadIdx.x;

    {
        int   cnt = g_counts[tid];
        float em  = (float)cnt * (1.0f / 32768.0f);
        float t   = em * logf(em + 1e-10f);
        sd[tid] = (double)t;
    }
    __syncthreads();
    for (int off = 512; off > 0; off >>= 1) {
        if (tid < off) sd[tid] += sd[tid + off];
        __syncthreads();
    }
    float perplexity = expf(-(float)sd[0]);
    __syncthreads();

    sd[tid] = g_losspart[tid];
    __syncthreads();
    for (int off = 512; off > 0; off >>= 1) {
        if (tid < off) sd[tid] += sd[tid + off];
        __syncthreads();
    }
    if (tid == 0 && has_extras) {
        double mean = sd[0] / (double)ZQ_SIZE;
        float  m    = (float)mean;
        float  loss = __fadd_rn(m, 0.25f * m);
        out[LOSS_OFF] = loss;
        out[PERP_OFF] = perplexity;
    }
}

// ---------------------------------------------------------------------------
extern "C" void kernel_launch(void* const* d_in, const int* in_sizes, int n_in,
                              void* d_out, int out_size) {
    const float* z   = (const float*)d_in[0];
    const float* emb = (const float*)d_in[1];
    float* out = (float*)d_out;
    int has_extras = (out_size >= FULL_OUT) ? 1 : 0;

    prep_kernel<<<133, 256>>>(z, emb);
    argmin_kernel<<<NROW / BS, 256>>>(z, emb);
    epilogue_kernel<<<NROW / 32, 256>>>(z, emb, out, has_extras);
    finalize_kernel<<<1, 1024>>>(out, has_extras);
}